// round 2
// baseline (speedup 1.0000x reference)
#include <cuda_runtime.h>

namespace {
constexpr int kH = 8;     // heads
constexpr int kB = 32;    // batch
constexpr int kN = 512;   // seq len
constexpr int kD = 256;   // input dim
constexpr int kd = 32;    // per-head dim
constexpr int kBN = kB * kN;            // 16384
constexpr int kHWaveElems = kB * kN * kD;        // 4,194,304
constexpr size_t kSmem2 = (8192 + 8448 + 256 + 128 + 16 + 8) * sizeof(float);  // 68192
constexpr size_t kSmem3 = (16384 + 16384) * sizeof(float);                     // 131072
}

// Scratch (device globals: allocation-free rule)
__device__ float g_Q[kH * kBN * kd];        // 16 MB [h][b*n][d]
__device__ float g_K[kH * kBN * kd];        // 16 MB
__device__ float g_V[kH * kBN * kd];        // 16 MB
__device__ float g_attn[kH * kB * kN * kN]; // 268 MB [h][b][n][m]
__device__ float g_heads[kH * kBN * kd];    // 16 MB [h][b*n][d]

// ---------------------------------------------------------------------------
// K1: QKV projection. One GEMM [16384 x 256] x [256 x 768].
// cols 0..255 -> Q, 256..511 -> K, 512..767 -> V; within each, head=(c>>5)&7.
// ---------------------------------------------------------------------------
__global__ __launch_bounds__(256) void qkv_kernel(
    const float* __restrict__ A, const float* __restrict__ Wq,
    const float* __restrict__ Wk, const float* __restrict__ Wv) {
  __shared__ float As[64][17];
  __shared__ float Bs[16][65];
  const int c0 = blockIdx.x * 64;          // 0..704
  const int row0 = blockIdx.y * 64;        // 0..16320
  const int which = c0 >> 8;               // uniform per block
  const float* __restrict__ W = (which == 0) ? Wq : (which == 1) ? Wk : Wv;
  float* __restrict__ O = (which == 0) ? g_Q : (which == 1) ? g_K : g_V;
  const int t = threadIdx.x;
  const int tx = t & 15, ty = t >> 4;

  float acc[4][4];
#pragma unroll
  for (int i = 0; i < 4; i++)
#pragma unroll
    for (int j = 0; j < 4; j++) acc[i][j] = 0.f;

  const int ar = t >> 2, akv = (t & 3) * 4;   // A tile: 64 rows x 16 k
  const int bk = t >> 4, bcv = (t & 15) * 4;  // B tile: 16 k x 64 cols
  const int bcc = c0 + bcv;
  const int bh = (bcc >> 5) & 7, bdd = bcc & 31;

  for (int k0 = 0; k0 < kD; k0 += 16) {
    float4 av = *reinterpret_cast<const float4*>(&A[(row0 + ar) * kD + k0 + akv]);
    As[ar][akv + 0] = av.x; As[ar][akv + 1] = av.y;
    As[ar][akv + 2] = av.z; As[ar][akv + 3] = av.w;
    float4 bv = *reinterpret_cast<const float4*>(&W[((bh << 8) + k0 + bk) * kd + bdd]);
    Bs[bk][bcv + 0] = bv.x; Bs[bk][bcv + 1] = bv.y;
    Bs[bk][bcv + 2] = bv.z; Bs[bk][bcv + 3] = bv.w;
    __syncthreads();
#pragma unroll
    for (int kk = 0; kk < 16; kk++) {
      float a[4], bb[4];
#pragma unroll
      for (int i = 0; i < 4; i++) a[i] = As[ty * 4 + i][kk];
#pragma unroll
      for (int j = 0; j < 4; j++) bb[j] = Bs[kk][tx * 4 + j];
#pragma unroll
      for (int i = 0; i < 4; i++)
#pragma unroll
        for (int j = 0; j < 4; j++) acc[i][j] = fmaf(a[i], bb[j], acc[i][j]);
    }
    __syncthreads();
  }

#pragma unroll
  for (int i = 0; i < 4; i++) {
    const int row = row0 + ty * 4 + i;
#pragma unroll
    for (int j = 0; j < 4; j++) {
      const int cc = c0 + tx * 4 + j;
      const int h = (cc >> 5) & 7, dd = cc & 31;
      O[(h * kBN + row) * kd + dd] = acc[i][j];
    }
  }
}

// ---------------------------------------------------------------------------
// K2: fused scores + score-aggregation MLP + aux passthrough.
// Grid (m_tile=16, n_tile=16, b=32), 256 threads.
// Phase A: warp = head, lane = query row n; K operand = broadcast LDS.
// Phase B: stage 32x32x8 scores via stride-33 smem (conflict-free both ways).
// Phase C: thread = (n-phase, m); x4 position register blocking so weight LDS
//          amortizes 1:4 vs FMA; aux passthrough written from the same read.
// ---------------------------------------------------------------------------
__global__ __launch_bounds__(256) void scores_mlp_kernel(
    const float* __restrict__ aux, const float* __restrict__ W1,
    const float* __restrict__ b1, const float* __restrict__ W2,
    const float* __restrict__ b2, float* __restrict__ out_aux) {
  extern __shared__ float sm[];
  float* Ks = sm;                   // [8][32][32] = 8192
  float* Ss = sm + 8192;            // [8][32][33] = 8448 (padded)
  float* W1s = Ss + 8448;           // 256
  float* W2s = W1s + 256;           // 128
  float* b1s = W2s + 128;           // 16
  float* b2s = b1s + 16;            // 8
  const int m0 = blockIdx.x * 32;
  const int n0 = blockIdx.y * 32;
  const int b = blockIdx.z;
  const int t = threadIdx.x;

  // cooperative K-tile load (coalesced float4)
#pragma unroll
  for (int i = 0; i < 8; i++) {
    const int idx = t + i * 256;  // float4 index 0..2047
    const int h = idx >> 8;
    const int rem = idx & 255;
    const int m = rem >> 3, d4 = (rem & 7) << 2;
    *reinterpret_cast<float4*>(&Ks[(h * 32 + m) * 32 + d4]) =
        *reinterpret_cast<const float4*>(&g_K[((h * kB + b) * kN + m0 + m) * kd + d4]);
  }
  W1s[t] = W1[t];
  if (t < 128) W2s[t] = W2[t];
  if (t < 16) b1s[t] = b1[t];
  if (t < 8) b2s[t] = b2[t];

  const int w = t >> 5;   // head
  const int ln = t & 31;  // query row within n-tile
  const float* __restrict__ Qrow = g_Q + ((w * kB + b) * kN + n0 + ln) * kd;
  const float* Kh = Ks + w * 1024;

  float s[32];
#pragma unroll
  for (int m = 0; m < 32; m++) s[m] = 0.f;
  __syncthreads();

#pragma unroll 1
  for (int db = 0; db < 4; db++) {
    const float4 q0 = *reinterpret_cast<const float4*>(&Qrow[db * 8]);
    const float4 q1 = *reinterpret_cast<const float4*>(&Qrow[db * 8 + 4]);
    const float qq[8] = {q0.x, q0.y, q0.z, q0.w, q1.x, q1.y, q1.z, q1.w};
#pragma unroll
    for (int dd = 0; dd < 8; dd++)
#pragma unroll
      for (int m = 0; m < 32; m++)
        s[m] = fmaf(qq[dd], Kh[m * 32 + db * 8 + dd], s[m]);
  }
#pragma unroll
  for (int m = 0; m < 32; m++) Ss[(w * 32 + ln) * 33 + m] = s[m];
  __syncthreads();

  // Phase C: thread -> (n = nl + 8p for p=0..3, m = mm); coalesced over mm.
  const int mm = t & 31, nl = t >> 5;
  float x[4][16];
#pragma unroll
  for (int p = 0; p < 4; p++) {
    const int n = nl + p * 8;
#pragma unroll
    for (int h = 0; h < 8; h++) x[p][h] = Ss[(h * 32 + n) * 33 + mm];
#pragma unroll
    for (int h = 0; h < 8; h++) {
      const int gi = ((h * kB + b) * kN + n0 + n) * kN + m0 + mm;
      const float a = aux[gi];
      out_aux[gi] = a;  // aux passthrough piggybacks on the read
      x[p][8 + h] = a;
    }
  }
  float hid[4][16];
#pragma unroll
  for (int p = 0; p < 4; p++)
#pragma unroll
    for (int j = 0; j < 16; j++) hid[p][j] = b1s[j];
#pragma unroll
  for (int i = 0; i < 16; i++)
#pragma unroll
    for (int j = 0; j < 16; j++) {
      const float wv = W1s[i * 16 + j];
#pragma unroll
      for (int p = 0; p < 4; p++) hid[p][j] = fmaf(x[p][i], wv, hid[p][j]);
    }
#pragma unroll
  for (int p = 0; p < 4; p++)
#pragma unroll
    for (int j = 0; j < 16; j++) hid[p][j] = fmaxf(hid[p][j], 0.f);

  float o[4][8];
#pragma unroll
  for (int p = 0; p < 4; p++)
#pragma unroll
    for (int k = 0; k < 8; k++) o[p][k] = b2s[k];
#pragma unroll
  for (int j = 0; j < 16; j++)
#pragma unroll
    for (int k = 0; k < 8; k++) {
      const float wv = W2s[j * 8 + k];
#pragma unroll
      for (int p = 0; p < 4; p++) o[p][k] = fmaf(hid[p][j], wv, o[p][k]);
    }
#pragma unroll
  for (int p = 0; p < 4; p++) {
    const int n = nl + p * 8;
#pragma unroll
    for (int k = 0; k < 8; k++)
      g_attn[((k * kB + b) * kN + n0 + n) * kN + m0 + mm] = o[p][k];
  }
}

// ---------------------------------------------------------------------------
// K3: full-row softmax + P@V. Grid (n_tile=16, b=32, h=8), 256 threads.
// Warp-per-row softmax, then thread = (4 rows, 1 d): P broadcast, V stride-1.
// ---------------------------------------------------------------------------
__global__ __launch_bounds__(256) void softmax_pv_kernel() {
  extern __shared__ float sm[];
  float* P = sm;           // [32][512]
  float* Vs = sm + 16384;  // [512][32]
  const int n0 = blockIdx.x * 32;
  const int b = blockIdx.y;
  const int h = blockIdx.z;
  const int t = threadIdx.x;

  const float* __restrict__ Vg = g_V + (h * kB + b) * kN * kd;
#pragma unroll
  for (int i = 0; i < 16; i++) {
    const int idx = (t + i * 256) << 2;
    *reinterpret_cast<float4*>(&Vs[idx]) = *reinterpret_cast<const float4*>(&Vg[idx]);
  }

  const int w = t >> 5, ln = t & 31;
  const float* __restrict__ attn_base = g_attn + ((h * kB + b) * kN + n0) * kN;
#pragma unroll 1
  for (int rp = 0; rp < 4; rp++) {
    const int n = w + rp * 8;
    const float* __restrict__ rowp = attn_base + n * kN;
    float a[16];
#pragma unroll
    for (int i = 0; i < 16; i++) a[i] = rowp[ln + i * 32];
    float mx = a[0];
#pragma unroll
    for (int i = 1; i < 16; i++) mx = fmaxf(mx, a[i]);
#pragma unroll
    for (int o = 16; o > 0; o >>= 1) mx = fmaxf(mx, __shfl_xor_sync(0xffffffffu, mx, o));
    float ssum = 0.f;
#pragma unroll
    for (int i = 0; i < 16; i++) {
      a[i] = __expf(a[i] - mx);
      ssum += a[i];
    }
#pragma unroll
    for (int o = 16; o > 0; o >>= 1) ssum += __shfl_xor_sync(0xffffffffu, ssum, o);
    const float inv = 1.f / ssum;
#pragma unroll
    for (int i = 0; i < 16; i++) P[n * kN + ln + i * 32] = a[i] * inv;
  }
  __syncthreads();

  const int d = t & 31, rg = t >> 5;  // rows rg*4..rg*4+3, column d
  float acc[4] = {0.f, 0.f, 0.f, 0.f};
  const float* Prow = P + rg * 4 * kN;
#pragma unroll 4
  for (int m = 0; m < kN; m++) {
    const float v = Vs[m * kd + d];
#pragma unroll
    for (int i = 0; i < 4; i++) acc[i] = fmaf(Prow[i * kN + m], v, acc[i]);
  }
  float* __restrict__ Og = g_heads + ((h * kB + b) * kN + n0 + rg * 4) * kd + d;
#pragma unroll
  for (int i = 0; i < 4; i++) Og[i * kd] = acc[i];
}

// ---------------------------------------------------------------------------
// K4: output projection. k = h*32+d is exactly Wout's row index, so this is
// a standard GEMM [16384 x 256] x [256 x 256]; only the A-tile gather is
// per-head strided (contiguous float4 within a 16-wide k-slab).
// ---------------------------------------------------------------------------
__global__ __launch_bounds__(256) void outproj_kernel(
    const float* __restrict__ Wout, float* __restrict__ out) {
  __shared__ float As[64][17];
  __shared__ float Bs[16][65];
  const int c0 = blockIdx.x * 64;
  const int row0 = blockIdx.y * 64;
  const int t = threadIdx.x;
  const int tx = t & 15, ty = t >> 4;

  float acc[4][4];
#pragma unroll
  for (int i = 0; i < 4; i++)
#pragma unroll
    for (int j = 0; j < 4; j++) acc[i][j] = 0.f;

  const int ar = t >> 2, akv = (t & 3) * 4;
  const int bk = t >> 4, bcv = (t & 15) * 4;

  for (int k0 = 0; k0 < kD; k0 += 16) {
    const int k = k0 + akv;
    const int h = k >> 5, dd = k & 31;
    float4 av = *reinterpret_cast<const float4*>(
        &g_heads[(h * kBN + row0 + ar) * kd + dd]);
    As[ar][akv + 0] = av.x; As[ar][akv + 1] = av.y;
    As[ar][akv + 2] = av.z; As[ar][akv + 3] = av.w;
    float4 bv = *reinterpret_cast<const float4*>(&Wout[(k0 + bk) * kD + c0 + bcv]);
    Bs[bk][bcv + 0] = bv.x; Bs[bk][bcv + 1] = bv.y;
    Bs[bk][bcv + 2] = bv.z; Bs[bk][bcv + 3] = bv.w;
    __syncthreads();
#pragma unroll
    for (int kk = 0; kk < 16; kk++) {
      float a[4], bb[4];
#pragma unroll
      for (int i = 0; i < 4; i++) a[i] = As[ty * 4 + i][kk];
#pragma unroll
      for (int j = 0; j < 4; j++) bb[j] = Bs[kk][tx * 4 + j];
#pragma unroll
      for (int i = 0; i < 4; i++)
#pragma unroll
        for (int j = 0; j < 4; j++) acc[i][j] = fmaf(a[i], bb[j], acc[i][j]);
    }
    __syncthreads();
  }

#pragma unroll
  for (int i = 0; i < 4; i++)
#pragma unroll
    for (int j = 0; j < 4; j++)
      out[(row0 + ty * 4 + i) * kD + c0 + tx * 4 + j] = acc[i][j];
}

extern "C" void kernel_launch(void* const* d_in, const int* in_sizes, int n_in,
                              void* d_out, int out_size) {
  const float* h_fea = (const float*)d_in[0];
  const float* aux   = (const float*)d_in[1];
  const float* Wq    = (const float*)d_in[2];
  const float* Wk    = (const float*)d_in[3];
  const float* Wv    = (const float*)d_in[4];
  const float* W1    = (const float*)d_in[5];
  const float* b1    = (const float*)d_in[6];
  const float* W2    = (const float*)d_in[7];
  const float* b2    = (const float*)d_in[8];
  const float* Wout  = (const float*)d_in[9];
  float* out = (float*)d_out;            // h_wave [B,N,D]
  float* out_aux = out + kHWaveElems;    // aux passthrough [H,B,N,N]

  cudaFuncSetAttribute(scores_mlp_kernel,
                       cudaFuncAttributeMaxDynamicSharedMemorySize, (int)kSmem2);
  cudaFuncSetAttribute(softmax_pv_kernel,
                       cudaFuncAttributeMaxDynamicSharedMemorySize, (int)kSmem3);

  qkv_kernel<<<dim3(12, 256), 256>>>(h_fea, Wq, Wk, Wv);
  scores_mlp_kernel<<<dim3(16, 16, 32), 256, kSmem2>>>(aux, W1, b1, W2, b2, out_aux);
  softmax_pv_kernel<<<dim3(16, 32, 8), 256, kSmem3>>>();
  outproj_kernel<<<dim3(4, 256), 256>>>(Wout, out);
}

// round 3
// speedup vs baseline: 1.0485x; 1.0485x over previous
#include <cuda_runtime.h>

namespace {
constexpr int kH = 8;
constexpr int kB = 32;
constexpr int kN = 512;
constexpr int kD = 256;
constexpr int kd = 32;
constexpr int kBN = kB * kN;              // 16384
constexpr int kHWaveElems = kB * kN * kD; // 4,194,304
// K3 dynamic smem: Ps[64][134] + VsT[32][134] + mx[64] + inv[64]
constexpr int kS3F = 64 * 134 + 32 * 134 + 64 + 64;
constexpr size_t kSmem3 = kS3F * sizeof(float);
}

using ull = unsigned long long;

__device__ __forceinline__ void fma2(ull& d, ull a, ull b) {
  asm("fma.rn.f32x2 %0, %1, %2, %0;" : "+l"(d) : "l"(a), "l"(b));
}
__device__ __forceinline__ ull pack2(float lo, float hi) {
  ull r;
  asm("mov.b64 %0, {%1, %2};" : "=l"(r) : "f"(lo), "f"(hi));
  return r;
}
__device__ __forceinline__ float2 unpack2(ull v) {
  float2 r;
  asm("mov.b64 {%0, %1}, %2;" : "=f"(r.x), "=f"(r.y) : "l"(v));
  return r;
}

// Scratch (device globals: allocation-free rule)
__device__ float g_Q[kH * kBN * kd];
__device__ float g_K[kH * kBN * kd];
__device__ float g_V[kH * kBN * kd];
__device__ float g_attn[kH * kB * kN * kN];  // 268 MB [h][b][n][m]
__device__ float g_heads[kH * kBN * kd];

// ---------------------------------------------------------------------------
// Shared f32x2 SGEMM body: 128 rows x 64 cols per block, 256 threads,
// per-thread 8 rows x 4 cols (16 f32x2 accumulators), k-chunk 16.
// As2 holds duplicated (a,a) pairs k-major (stride 260); Bs natural (stride 64).
// ---------------------------------------------------------------------------
#define GEMM_SMEM                       \
  __shared__ __align__(16) float As2[16 * 260]; \
  __shared__ __align__(16) float Bs[16 * 64];

#define GEMM_STAGE(ra0, ra1, rb)                                        \
  {                                                                     \
    float va0[4] = {ra0.x, ra0.y, ra0.z, ra0.w};                        \
    float va1[4] = {ra1.x, ra1.y, ra1.z, ra1.w};                        \
    _Pragma("unroll") for (int j = 0; j < 4; j++) {                     \
      *(ull*)&As2[(akq0 + j) * 260 + 2 * arow0] = pack2(va0[j], va0[j]); \
      *(ull*)&As2[(akq1 + j) * 260 + 2 * arow1] = pack2(va1[j], va1[j]); \
    }                                                                   \
    *(float4*)&Bs[bkk * 64 + cc] = rb;                                  \
  }

#define GEMM_COMPUTE(acc)                                         \
  _Pragma("unroll") for (int kk = 0; kk < 16; kk++) {             \
    ulonglong2 b2 = *(const ulonglong2*)&Bs[kk * 64 + tx * 4];    \
    _Pragma("unroll") for (int rg = 0; rg < 4; rg++) {            \
      ulonglong2 a2 =                                             \
          *(const ulonglong2*)&As2[kk * 260 + ty * 16 + rg * 4];  \
      fma2(acc[2 * rg][0], a2.x, b2.x);                           \
      fma2(acc[2 * rg][1], a2.x, b2.y);                           \
      fma2(acc[2 * rg + 1][0], a2.y, b2.x);                       \
      fma2(acc[2 * rg + 1][1], a2.y, b2.y);                       \
    }                                                             \
  }

// ---------------------------------------------------------------------------
// K1: QKV projection. [16384 x 256] x [256 x 768].
// ---------------------------------------------------------------------------
__global__ __launch_bounds__(256) void qkv_kernel(
    const float* __restrict__ A, const float* __restrict__ Wq,
    const float* __restrict__ Wk, const float* __restrict__ Wv) {
  GEMM_SMEM
  const int c0 = blockIdx.x * 64;
  const int row0 = blockIdx.y * 128;
  const int which = c0 >> 8;
  const float* __restrict__ W = (which == 0) ? Wq : (which == 1) ? Wk : Wv;
  float* __restrict__ O = (which == 0) ? g_Q : (which == 1) ? g_K : g_V;
  const int t = threadIdx.x;
  const int tx = t & 15, ty = t >> 4;

  const int idx0 = t, idx1 = t + 256;
  const int arow0 = idx0 >> 2, akq0 = (idx0 & 3) * 4;
  const int arow1 = idx1 >> 2, akq1 = (idx1 & 3) * 4;
  const int bkk = t >> 4, cc = (t & 15) * 4;
  const int c = c0 + cc;
  const int bh = (c >> 5) & 7, bdd = c & 31;

  ull acc[8][2];
#pragma unroll
  for (int i = 0; i < 8; i++) acc[i][0] = acc[i][1] = 0ULL;

  float4 ra0 = *(const float4*)&A[(row0 + arow0) * kD + akq0];
  float4 ra1 = *(const float4*)&A[(row0 + arow1) * kD + akq1];
  float4 rb = *(const float4*)&W[((bh << 8) + bkk) * kd + bdd];

  for (int k0 = 0; k0 < kD; k0 += 16) {
    GEMM_STAGE(ra0, ra1, rb)
    __syncthreads();
    if (k0 + 16 < kD) {
      ra0 = *(const float4*)&A[(row0 + arow0) * kD + k0 + 16 + akq0];
      ra1 = *(const float4*)&A[(row0 + arow1) * kD + k0 + 16 + akq1];
      rb = *(const float4*)&W[((bh << 8) + k0 + 16 + bkk) * kd + bdd];
    }
    GEMM_COMPUTE(acc)
    __syncthreads();
  }

#pragma unroll
  for (int rr = 0; rr < 8; rr++) {
    const int row = row0 + ty * 8 + rr;
#pragma unroll
    for (int p = 0; p < 2; p++) {
      const int oc = c0 + tx * 4 + 2 * p;
      const int h = (oc >> 5) & 7, dd = oc & 31;
      *(ull*)&O[(h * kBN + row) * kd + dd] = acc[rr][p];
    }
  }
}

// ---------------------------------------------------------------------------
// K2: fused scores + score-aggregation MLP + aux passthrough.
// Grid (16 m-tiles, 16 n-tiles, 32 b), 256 threads.
// Phase A: warp=head, lane=query row; K stored d-major so m-pairs are native.
// Phase B: stage scores (stride-34 pairs) in smem unioned with the K tile.
// Phase C: MLP paired over output channel j; x4 position register blocking.
// ---------------------------------------------------------------------------
__global__ __launch_bounds__(256) void scores_mlp_kernel(
    const float* __restrict__ aux, const float* __restrict__ W1,
    const float* __restrict__ b1, const float* __restrict__ W2,
    const float* __restrict__ b2, float* __restrict__ out_aux) {
  __shared__ __align__(16) float U[8 * 32 * 36];  // KsT then Ss (union)
  __shared__ __align__(16) float W1s[256];
  __shared__ __align__(16) float W2s[128];
  __shared__ __align__(16) float b1s[16];
  __shared__ __align__(16) float b2s[8];
  const int m0 = blockIdx.x * 32;
  const int n0 = blockIdx.y * 32;
  const int b = blockIdx.z;
  const int t = threadIdx.x;

  // Fill KsT[h][dd][m] (stride 36) from g_K (coalesced float4 along dd)
#pragma unroll
  for (int i = 0; i < 8; i++) {
    const int idx = t + 256 * i;  // float4 index 0..2047
    const int h = idx >> 8;
    const int rem = idx & 255;
    const int m = rem >> 3, d4 = (rem & 7) * 4;
    float4 v = *(const float4*)&g_K[((h * kB + b) * kN + m0 + m) * kd + d4];
    U[(h * 32 + d4 + 0) * 36 + m] = v.x;
    U[(h * 32 + d4 + 1) * 36 + m] = v.y;
    U[(h * 32 + d4 + 2) * 36 + m] = v.z;
    U[(h * 32 + d4 + 3) * 36 + m] = v.w;
  }
  W1s[t & 255] = W1[t & 255];
  if (t < 128) W2s[t] = W2[t];
  if (t < 16) b1s[t] = b1[t];
  if (t < 8) b2s[t] = b2[t];

  const int w = t >> 5, ln = t & 31;
  const float* __restrict__ Qrow = g_Q + ((w * kB + b) * kN + n0 + ln) * kd;

  ull acc2[16];
#pragma unroll
  for (int i = 0; i < 16; i++) acc2[i] = 0ULL;
  __syncthreads();

#pragma unroll 1
  for (int db = 0; db < 4; db++) {
    const float4 q0 = *(const float4*)&Qrow[db * 8];
    const float4 q1 = *(const float4*)&Qrow[db * 8 + 4];
    const float qq[8] = {q0.x, q0.y, q0.z, q0.w, q1.x, q1.y, q1.z, q1.w};
#pragma unroll
    for (int dd = 0; dd < 8; dd++) {
      const ull qp = pack2(qq[dd], qq[dd]);
      const float* kp = &U[(w * 32 + db * 8 + dd) * 36];
#pragma unroll
      for (int mp4 = 0; mp4 < 8; mp4++) {
        ulonglong2 k2 = *(const ulonglong2*)(kp + mp4 * 4);
        fma2(acc2[2 * mp4], qp, k2.x);
        fma2(acc2[2 * mp4 + 1], qp, k2.y);
      }
    }
  }
  __syncthreads();  // KsT dead; reuse U as Ss[h][n][m] stride 34
#pragma unroll
  for (int mp = 0; mp < 16; mp++)
    *(ull*)&U[(w * 32 + ln) * 34 + 2 * mp] = acc2[mp];
  __syncthreads();

  // Phase C: position (n = nl + 8p, m = mm)
  const int mm = t & 31, nl = t >> 5;
  float av[4][8];
#pragma unroll
  for (int p = 0; p < 4; p++) {
    const int n = nl + 8 * p;
#pragma unroll
    for (int h = 0; h < 8; h++) {
      const int gi = ((h * kB + b) * kN + n0 + n) * kN + m0 + mm;
      const float a = aux[gi];
      out_aux[gi] = a;
      av[p][h] = a;
    }
  }
  ull hid2[4][8];
#pragma unroll
  for (int j2 = 0; j2 < 8; j2++) {
    const ull bp = *(const ull*)&b1s[2 * j2];
#pragma unroll
    for (int p = 0; p < 4; p++) hid2[p][j2] = bp;
  }
#pragma unroll
  for (int i = 0; i < 16; i++) {
    ull xp[4];
#pragma unroll
    for (int p = 0; p < 4; p++) {
      float xv;
      if (i < 8)
        xv = U[(i * 32 + nl + 8 * p) * 34 + mm];
      else
        xv = av[p][i - 8];
      xp[p] = pack2(xv, xv);
    }
#pragma unroll
    for (int j2 = 0; j2 < 8; j2++) {
      const ull w2 = *(const ull*)&W1s[i * 16 + 2 * j2];
#pragma unroll
      for (int p = 0; p < 4; p++) fma2(hid2[p][j2], xp[p], w2);
    }
  }
  ull o2[4][4];
#pragma unroll
  for (int k2 = 0; k2 < 4; k2++) {
    const ull bp = *(const ull*)&b2s[2 * k2];
#pragma unroll
    for (int p = 0; p < 4; p++) o2[p][k2] = bp;
  }
#pragma unroll
  for (int j2 = 0; j2 < 8; j2++) {
#pragma unroll
    for (int p = 0; p < 4; p++) {
      float2 hv = unpack2(hid2[p][j2]);
      hv.x = fmaxf(hv.x, 0.f);
      hv.y = fmaxf(hv.y, 0.f);
      const ull hp0 = pack2(hv.x, hv.x);
      const ull hp1 = pack2(hv.y, hv.y);
#pragma unroll
      for (int k2 = 0; k2 < 4; k2++) {
        fma2(o2[p][k2], hp0, *(const ull*)&W2s[(2 * j2) * 8 + 2 * k2]);
        fma2(o2[p][k2], hp1, *(const ull*)&W2s[(2 * j2 + 1) * 8 + 2 * k2]);
      }
    }
  }
#pragma unroll
  for (int p = 0; p < 4; p++) {
    const int n = nl + 8 * p;
#pragma unroll
    for (int k2 = 0; k2 < 4; k2++) {
      float2 ov = unpack2(o2[p][k2]);
      g_attn[(((2 * k2) * kB + b) * kN + n0 + n) * kN + m0 + mm] = ov.x;
      g_attn[(((2 * k2 + 1) * kB + b) * kN + n0 + n) * kN + m0 + mm] = ov.y;
    }
  }
}

// ---------------------------------------------------------------------------
// K3: two-pass softmax + P@V, f32x2 paired over the reduction index m.
// Grid (8 n-tiles of 64, 32 b, 8 h), 128 threads.
// Pass 1: warp-per-row stats (max, 1/sum). Pass 2: 4 chunks of 128 m:
// recompute p=exp(a-mx)*inv into Ps (stride 134), V^T chunk (stride 134),
// per-thread 4 rows x 4 d: 16 FMA2 : 8 LDS.64 per pair-step.
// ---------------------------------------------------------------------------
__global__ __launch_bounds__(128) void softmax_pv_kernel() {
  extern __shared__ __align__(16) float sm[];
  float* Ps = sm;                   // [64][134]
  float* VsT = sm + 64 * 134;      // [32][134]
  float* mxs = VsT + 32 * 134;     // [64]
  float* invs = mxs + 64;          // [64]
  const int n0 = blockIdx.x * 64;
  const int b = blockIdx.y;
  const int h = blockIdx.z;
  const int t = threadIdx.x;
  const int w = t >> 5, ln = t & 31;

  const float* __restrict__ attn = g_attn + ((h * kB + b) * kN + n0) * kN;
#pragma unroll 1
  for (int rr = 0; rr < 16; rr++) {
    const int n = w * 16 + rr;
    const float4* rowp = (const float4*)(attn + n * kN);
    float a[16];
#pragma unroll
    for (int i4 = 0; i4 < 4; i4++) {
      float4 v = rowp[ln + 32 * i4];
      a[i4 * 4 + 0] = v.x; a[i4 * 4 + 1] = v.y;
      a[i4 * 4 + 2] = v.z; a[i4 * 4 + 3] = v.w;
    }
    float mx = a[0];
#pragma unroll
    for (int i = 1; i < 16; i++) mx = fmaxf(mx, a[i]);
#pragma unroll
    for (int o = 16; o > 0; o >>= 1) mx = fmaxf(mx, __shfl_xor_sync(0xffffffffu, mx, o));
    float ssum = 0.f;
#pragma unroll
    for (int i = 0; i < 16; i++) ssum += __expf(a[i] - mx);
#pragma unroll
    for (int o = 16; o > 0; o >>= 1) ssum += __shfl_xor_sync(0xffffffffu, ssum, o);
    if (ln == 0) { mxs[n] = mx; invs[n] = 1.f / ssum; }
  }
  __syncthreads();

  const int tn = t >> 3;  // 0..15 -> rows tn*4..+3
  const int td = t & 7;   // 0..7  -> d = td*4..+3
  ull acc2[4][4];
#pragma unroll
  for (int r = 0; r < 4; r++)
#pragma unroll
    for (int s = 0; s < 4; s++) acc2[r][s] = 0ULL;

  const float* __restrict__ Vg = g_V + (h * kB + b) * kN * kd;
#pragma unroll 1
  for (int cch = 0; cch < 4; cch++) {
    if (cch) __syncthreads();
    // Ps chunk: 64 rows x 128 m, exp on the fly
#pragma unroll
    for (int i = 0; i < 16; i++) {
      const int idx = t + 128 * i;  // float4 idx 0..2047
      const int n = idx >> 5;
      const int m4 = (idx & 31) * 4;
      float4 v = *(const float4*)&attn[n * kN + cch * 128 + m4];
      const float mxv = mxs[n], iv = invs[n];
      float* dst = &Ps[n * 134 + m4];
      *(ull*)(dst + 0) = pack2(__expf(v.x - mxv) * iv, __expf(v.y - mxv) * iv);
      *(ull*)(dst + 2) = pack2(__expf(v.z - mxv) * iv, __expf(v.w - mxv) * iv);
    }
    // V^T chunk: [d][m] stride 134
#pragma unroll
    for (int i = 0; i < 8; i++) {
      const int idx = t + 128 * i;  // 0..1023
      const int m = idx >> 3;
      const int d4 = (idx & 7) * 4;
      float4 v = *(const float4*)&Vg[(cch * 128 + m) * kd + d4];
      VsT[(d4 + 0) * 134 + m] = v.x;
      VsT[(d4 + 1) * 134 + m] = v.y;
      VsT[(d4 + 2) * 134 + m] = v.z;
      VsT[(d4 + 3) * 134 + m] = v.w;
    }
    __syncthreads();
#pragma unroll 2
    for (int mp = 0; mp < 64; mp++) {
      ull p2[4], v2[4];
#pragma unroll
      for (int r = 0; r < 4; r++)
        p2[r] = *(const ull*)&Ps[(tn * 4 + r) * 134 + 2 * mp];
#pragma unroll
      for (int s = 0; s < 4; s++)
        v2[s] = *(const ull*)&VsT[(td * 4 + s) * 134 + 2 * mp];
#pragma unroll
      for (int r = 0; r < 4; r++)
#pragma unroll
        for (int s = 0; s < 4; s++) fma2(acc2[r][s], p2[r], v2[s]);
    }
  }

#pragma unroll
  for (int r = 0; r < 4; r++) {
    const int n = n0 + tn * 4 + r;
    float4 o;
    float2 v0 = unpack2(acc2[r][0]), v1 = unpack2(acc2[r][1]);
    float2 v2 = unpack2(acc2[r][2]), v3 = unpack2(acc2[r][3]);
    o.x = v0.x + v0.y; o.y = v1.x + v1.y;
    o.z = v2.x + v2.y; o.w = v3.x + v3.y;
    *(float4*)&g_heads[((h * kB + b) * kN + n) * kd + td * 4] = o;
  }
}

// ---------------------------------------------------------------------------
// K4: output projection [16384 x 256] x [256 x 256] (k = h*32+d).
// ---------------------------------------------------------------------------
__global__ __launch_bounds__(256) void outproj_kernel(
    const float* __restrict__ Wout, float* __restrict__ out) {
  GEMM_SMEM
  const int c0 = blockIdx.x * 64;
  const int row0 = blockIdx.y * 128;
  const int t = threadIdx.x;
  const int tx = t & 15, ty = t >> 4;

  const int idx0 = t, idx1 = t + 256;
  const int arow0 = idx0 >> 2, akq0 = (idx0 & 3) * 4;
  const int arow1 = idx1 >> 2, akq1 = (idx1 & 3) * 4;
  const int bkk = t >> 4, cc = (t & 15) * 4;

  ull acc[8][2];
#pragma unroll
  for (int i = 0; i < 8; i++) acc[i][0] = acc[i][1] = 0ULL;

  auto loadA = [&](int row, int k) {
    const int h = k >> 5, dd = k & 31;
    return *(const float4*)&g_heads[(h * kBN + row0 + row) * kd + dd];
  };
  float4 ra0 = loadA(arow0, akq0);
  float4 ra1 = loadA(arow1, akq1);
  float4 rb = *(const float4*)&Wout[bkk * kD + c0 + cc];

  for (int k0 = 0; k0 < kD; k0 += 16) {
    GEMM_STAGE(ra0, ra1, rb)
    __syncthreads();
    if (k0 + 16 < kD) {
      ra0 = loadA(arow0, k0 + 16 + akq0);
      ra1 = loadA(arow1, k0 + 16 + akq1);
      rb = *(const float4*)&Wout[(k0 + 16 + bkk) * kD + c0 + cc];
    }
    GEMM_COMPUTE(acc)
    __syncthreads();
  }

#pragma unroll
  for (int rr = 0; rr < 8; rr++) {
    const int row = row0 + ty * 8 + rr;
#pragma unroll
    for (int p = 0; p < 2; p++)
      *(ull*)&out[row * kD + c0 + tx * 4 + 2 * p] = acc[rr][p];
  }
}

extern "C" void kernel_launch(void* const* d_in, const int* in_sizes, int n_in,
                              void* d_out, int out_size) {
  const float* h_fea = (const float*)d_in[0];
  const float* aux   = (const float*)d_in[1];
  const float* Wq    = (const float*)d_in[2];
  const float* Wk    = (const float*)d_in[3];
  const float* Wv    = (const float*)d_in[4];
  const float* W1    = (const float*)d_in[5];
  const float* b1    = (const float*)d_in[6];
  const float* W2    = (const float*)d_in[7];
  const float* b2    = (const float*)d_in[8];
  const float* Wout  = (const float*)d_in[9];
  float* out = (float*)d_out;
  float* out_aux = out + kHWaveElems;

  cudaFuncSetAttribute(softmax_pv_kernel,
                       cudaFuncAttributeMaxDynamicSharedMemorySize, (int)kSmem3);

  qkv_kernel<<<dim3(12, 128), 256>>>(h_fea, Wq, Wk, Wv);
  scores_mlp_kernel<<<dim3(16, 16, 32), 256>>>(aux, W1, b1, W2, b2, out_aux);
  softmax_pv_kernel<<<dim3(8, 32, 8), 128, kSmem3>>>();
  outproj_kernel<<<dim3(4, 128), 256>>>(Wout, out);
}